// round 8
// baseline (speedup 1.0000x reference)
#include <cuda_runtime.h>
#include <cstdint>

// Fixed problem shape
#define HH 128
#define WW 240
#define NG 40
#define CPG 8
#define DD 48
#define PADL 48
#define NPOS (WW + PADL)   // 288 positions per smem row
#define ROWA 292           // stride ≡ 4 (mod 8): kh halves hit disjoint bank sets
#define TPB 128

#define GWC_BLOCKS (HH * NG)   // 5120
#define CAT_BLOCKS (24 * DD)   // 1152
#define MIX_LIMIT (CAT_BLOCKS * 5)   // 5760
#define TOTAL_BLOCKS (GWC_BLOCKS + CAT_BLOCKS)  // 6272

typedef unsigned long long ull;

__device__ __forceinline__ void stcs4(float* p, float4 v) { __stcs((float4*)p, v); }
__device__ __forceinline__ void stcs2(float* p, float2 v) { __stcs((float2*)p, v); }

// pack two f32 into a 64-bit register pair
__device__ __forceinline__ ull pk(float a, float b) {
    ull r;
    asm("mov.b64 %0, {%1, %2};" : "=l"(r) : "f"(a), "f"(b));
    return r;
}
__device__ __forceinline__ float2 upk(ull a) {
    float2 f;
    asm("mov.b64 {%0, %1}, %2;" : "=f"(f.x), "=f"(f.y) : "l"(a));
    return f;
}
// packed dual-FMA (Blackwell f32x2)
__device__ __forceinline__ ull ffma2(ull a, ull b, ull c) {
    ull d;
    asm("fma.rn.f32x2 %0, %1, %2, %3;" : "=l"(d) : "l"(a), "l"(b), "l"(c));
    return d;
}

__global__ __launch_bounds__(TPB, 8)
void fused_kernel(const float* __restrict__ ref, const float* __restrict__ tgt,
                  const float* __restrict__ refc, const float* __restrict__ tgtc,
                  float* __restrict__ out) {
    __shared__ float s[CPG * ROWA];   // 9344 B

    const int bid = blockIdx.x;
    const int tid = threadIdx.x;

    bool is_cat;
    int wid_;
    if (bid < MIX_LIMIT) {
        int q5 = bid / 5, r5 = bid - q5 * 5;
        is_cat = (r5 == 4);
        wid_ = is_cat ? q5 : (q5 * 4 + r5);
    } else {
        is_cat = false;
        wid_ = 4 * CAT_BLOCKS + (bid - MIX_LIMIT);
    }

    if (!is_cat) {
        // ======== gwc block: one (h, group); lane pairs split channels ========
        const int g = wid_ % NG;
        const int h = wid_ / NG;

        // fill smem rows (row = channel, stride 292, left zero pad), float4 path
        for (int i = tid; i < CPG * (NPOS / 4); i += TPB) {
            const int c = i / (NPOS / 4), j = i - c * (NPOS / 4);
            const int p4 = j * 4;
            float4 v;
            if (p4 >= PADL)
                v = *(const float4*)(tgt + (((size_t)(g * CPG + c)) * HH + h) * WW + (p4 - PADL));
            else
                v = make_float4(0.f, 0.f, 0.f, 0.f);
            *(float4*)(s + c * ROWA + p4) = v;
        }
        __syncthreads();

        const int kh = tid & 1;            // 0 -> channels 0..3, 1 -> channels 4..7
        int q = tid >> 1;                  // w-quad id 0..63
        const bool active = (q < 60);
        if (q > 59) q = 59;                // keep warps converged for shfl
        const int w4 = q * 4;

        // ref: 4 channels x 4 w, x1/8 folded, packed as f32x2 pairs (16 regs)
        ull rp01[4], rp23[4];
#pragma unroll
        for (int k = 0; k < 4; ++k) {
            const int c = kh * 4 + k;
            float4 v = *(const float4*)(ref + (((size_t)(g * CPG + c)) * HH + h) * WW + w4);
            rp01[k] = pk(v.x * 0.125f, v.y * 0.125f);
            rp23[k] = pk(v.z * 0.125f, v.w * 0.125f);
        }

        // base of this thread's 4 channel rows; per-k offsets are compile-time
        const float* sbase = s + (kh * 4) * ROWA;

        float4 A[4], B[4];                 // rolling quads (32 regs)
#pragma unroll
        for (int k = 0; k < 4; ++k)
            B[k] = *(const float4*)(sbase + k * ROWA + PADL + w4);

        int pb = PADL + w4 - 4;            // quad-aligned, >= 0 for all groups
        float* op = out + ((size_t)g * DD * HH + h) * WW + w4 + 2 * kh;

        // epilogue: pair exchange + packed add + 8B streaming store
#define GWC_EPI(a01, a23)                                               \
        {                                                               \
            float2 sf = upk(kh ? (a01) : (a23));                        \
            float u0 = __shfl_xor_sync(0xffffffffu, sf.x, 1);           \
            float u1 = __shfl_xor_sync(0xffffffffu, sf.y, 1);           \
            if (active) {                                               \
                float2 own = upk(kh ? (a23) : (a01));                   \
                float2 o; o.x = own.x + u0; o.y = own.y + u1;           \
                stcs2(op, o);                                           \
            }                                                           \
            op += HH * WW;                                              \
        }
        // one disparity sub-step; F = [LO|HI], output j uses F[4 + j - t]
#define GWC_T(LO, HI, P01, P23)                                         \
        {                                                               \
            ull a01 = 0ull, a23 = 0ull;                                 \
            _Pragma("unroll")                                           \
            for (int k = 0; k < 4; ++k) {                               \
                a01 = ffma2(rp01[k], (P01), a01);                       \
                a23 = ffma2(rp23[k], (P23), a23);                       \
            }                                                           \
            GWC_EPI(a01, a23)                                           \
        }
#define GWC_T0(LO, HI) GWC_T(LO, HI, pk(HI[k].x, HI[k].y), pk(HI[k].z, HI[k].w))
#define GWC_T1(LO, HI) GWC_T(LO, HI, pk(LO[k].w, HI[k].x), pk(HI[k].y, HI[k].z))
#define GWC_T2(LO, HI) GWC_T(LO, HI, pk(LO[k].z, LO[k].w), pk(HI[k].x, HI[k].y))
#define GWC_T3(LO, HI) GWC_T(LO, HI, pk(LO[k].y, LO[k].z), pk(LO[k].w, HI[k].x))

#pragma unroll
        for (int dp = 0; dp < DD / 8; ++dp) {
            // group A: lo = A (newly loaded), hi = B
#pragma unroll
            for (int k = 0; k < 4; ++k) A[k] = *(const float4*)(sbase + k * ROWA + pb);
            GWC_T0(A, B) GWC_T1(A, B) GWC_T2(A, B) GWC_T3(A, B)
            pb -= 4;
            // group B: lo = B (newly loaded), hi = A
#pragma unroll
            for (int k = 0; k < 4; ++k) B[k] = *(const float4*)(sbase + k * ROWA + pb);
            GWC_T0(B, A) GWC_T1(B, A) GWC_T2(B, A) GWC_T3(B, A)
            pb -= 4;
        }
#undef GWC_T0
#undef GWC_T1
#undef GWC_T2
#undef GWC_T3
#undef GWC_T
#undef GWC_EPI
    } else {
        // ======== concat block: one (c, d) plane, 120 threads ========
        const int d = wid_ % DD;
        const int c = wid_ / DD;
        if (tid >= 120) return;
        const int wq   = tid % 60;
        const int half = tid / 60;
        const int wb = wq * 4;
        const int h0 = half * 64;

        float* ob = out + ((((size_t)(NG + c) * DD + d) * HH) + h0) * WW + wb;

        if (c < 12) {
            // masked copy of ref_concat plane
            const bool m0 = (wb + 0 >= d), m1 = (wb + 1 >= d),
                       m2 = (wb + 2 >= d), m3 = (wb + 3 >= d);
            const float* ib = refc + (((size_t)c * HH) + h0) * WW + wb;
#pragma unroll 4
            for (int h = 0; h < 64; ++h) {
                float4 x = *(const float4*)(ib + h * WW);
                float4 v;
                v.x = m0 ? x.x : 0.f;
                v.y = m1 ? x.y : 0.f;
                v.z = m2 ? x.z : 0.f;
                v.w = m3 ? x.w : 0.f;
                stcs4(ob + h * WW, v);
            }
        } else {
            // right-shifted tgt_concat plane via aligned quad pair + uniform select
            const float* base = tgtc + (((size_t)(c - 12) * HH) + h0) * WW;
            const int sh = d & 3;
            if (sh == 0) {
                const int lo = wb - d;                 // quad aligned
                if (lo >= 0) {
                    const float* ib = base + lo;
#pragma unroll 4
                    for (int h = 0; h < 64; ++h)
                        stcs4(ob + h * WW, *(const float4*)(ib + h * WW));
                } else {                               // fully masked lane
                    float4 z = make_float4(0.f, 0.f, 0.f, 0.f);
#pragma unroll 4
                    for (int h = 0; h < 64; ++h)
                        stcs4(ob + h * WW, z);
                }
            } else {
                const int off = 4 - sh;                // 1..3
                const int lo = wb - d - off;           // quad aligned
                const int hi4 = lo + 4;                // hi quad start (<= 236: in bounds)
                const bool ldlo = (lo >= 0), ldhi = (hi4 >= 0);
                const float4 z = make_float4(0.f, 0.f, 0.f, 0.f);
#pragma unroll 4
                for (int h = 0; h < 64; ++h) {
                    float4 L = ldlo ? *(const float4*)(base + h * WW + lo)  : z;
                    float4 H = ldhi ? *(const float4*)(base + h * WW + hi4) : z;
                    float4 v;
                    if (off == 1)      { v.x = L.y; v.y = L.z; v.z = L.w; v.w = H.x; }
                    else if (off == 2) { v.x = L.z; v.y = L.w; v.z = H.x; v.w = H.y; }
                    else               { v.x = L.w; v.y = H.x; v.z = H.y; v.w = H.z; }
                    stcs4(ob + h * WW, v);
                }
            }
        }
    }
}

extern "C" void kernel_launch(void* const* d_in, const int* in_sizes, int n_in,
                              void* d_out, int out_size) {
    const float* ref_gwc    = (const float*)d_in[0];
    const float* tgt_gwc    = (const float*)d_in[1];
    const float* ref_concat = (const float*)d_in[2];
    const float* tgt_concat = (const float*)d_in[3];
    float* out = (float*)d_out;

    fused_kernel<<<TOTAL_BLOCKS, TPB>>>(ref_gwc, tgt_gwc, ref_concat, tgt_concat, out);
}

// round 10
// speedup vs baseline: 1.0011x; 1.0011x over previous
#include <cuda_runtime.h>
#include <cstdint>

// Fixed problem shape
#define HH 128
#define WW 240
#define NG 40
#define CPG 8
#define DD 48
#define PADL 48
#define NPOS (WW + PADL)   // 288 positions per smem row
#define ROWA 292           // stride ≡ 4 (mod 8): kh halves hit disjoint bank sets
#define TPB 128

#define GWC_BLOCKS (HH * NG)   // 5120
#define CAT_BLOCKS (24 * DD)   // 1152
#define MIX_LIMIT (CAT_BLOCKS * 5)   // 5760
#define TOTAL_BLOCKS (GWC_BLOCKS + CAT_BLOCKS)  // 6272

__device__ __forceinline__ void stcs4(float* p, float4 v) { __stcs((float4*)p, v); }
__device__ __forceinline__ void stcs2(float* p, float2 v) { __stcs((float2*)p, v); }

__global__ __launch_bounds__(TPB, 6)
void fused_kernel(const float* __restrict__ ref, const float* __restrict__ tgt,
                  const float* __restrict__ refc, const float* __restrict__ tgtc,
                  float* __restrict__ out) {
    __shared__ float s[CPG * ROWA];   // 9344 B

    const int bid = blockIdx.x;
    const int tid = threadIdx.x;

    bool is_cat;
    int wid_;
    if (bid < MIX_LIMIT) {
        int q5 = bid / 5, r5 = bid - q5 * 5;
        is_cat = (r5 == 4);
        wid_ = is_cat ? q5 : (q5 * 4 + r5);
    } else {
        is_cat = false;
        wid_ = 4 * CAT_BLOCKS + (bid - MIX_LIMIT);
    }

    if (!is_cat) {
        // ======== gwc block: one (h, group); lane pairs split channels ========
        const int g = wid_ % NG;
        const int h = wid_ / NG;

        const int kh = tid & 1;            // 0 -> channels 0..3, 1 -> channels 4..7
        int q = tid >> 1;                  // w-quad id 0..63
        const bool active = (q < 60);
        if (q > 59) q = 59;                // keep warps converged for shfl
        const int w4 = q * 4;

        // ---- ref prefetch BEFORE the barrier: overlaps smem fill + sync ----
        float4 rv[4];
#pragma unroll
        for (int k = 0; k < 4; ++k)
            rv[k] = *(const float4*)(ref + (((size_t)(g * CPG + kh * 4 + k)) * HH + h) * WW + w4);

        // fill smem rows (row = channel, stride 292, left zero pad), float4 path
        for (int i = tid; i < CPG * (NPOS / 4); i += TPB) {
            const int c = i / (NPOS / 4), j = i - c * (NPOS / 4);
            const int p4 = j * 4;
            float4 v;
            if (p4 >= PADL)
                v = *(const float4*)(tgt + (((size_t)(g * CPG + c)) * HH + h) * WW + (p4 - PADL));
            else
                v = make_float4(0.f, 0.f, 0.f, 0.f);
            *(float4*)(s + c * ROWA + p4) = v;
        }
        __syncthreads();

        // ref with x1/8 folded (16 regs)
        float r[4][4];
#pragma unroll
        for (int k = 0; k < 4; ++k) {
            r[k][0] = rv[k].x * 0.125f; r[k][1] = rv[k].y * 0.125f;
            r[k][2] = rv[k].z * 0.125f; r[k][3] = rv[k].w * 0.125f;
        }

        const float* sbase = s + (kh * 4) * ROWA;

        // 3 rotating quad buffers (48 regs): preload runs a full group ahead,
        // so the 29-cycle LDS never sits on the FMA critical path.
        float4 W0[4], W1[4], W2[4];
        const int P = PADL + w4;
#pragma unroll
        for (int k = 0; k < 4; ++k) {
            W0[k] = *(const float4*)(sbase + k * ROWA + P);       // hi, group 0
            W1[k] = *(const float4*)(sbase + k * ROWA + P - 4);   // lo, group 0
        }

        float* op = out + ((size_t)g * DD * HH + h) * WW + w4 + 2 * kh;

        // one disparity sub-step: F = [LO|HI] flattened, out j uses F[4 + j - T]
#define GWC_STEP(LO, HI, T)                                                     \
        {                                                                       \
            float a0 = 0.f, a1 = 0.f, a2 = 0.f, a3 = 0.f;                       \
            _Pragma("unroll")                                                   \
            for (int k = 0; k < 4; ++k) {                                       \
                const float F[8] = { LO[k].x, LO[k].y, LO[k].z, LO[k].w,        \
                                     HI[k].x, HI[k].y, HI[k].z, HI[k].w };      \
                a0 += r[k][0] * F[4 + 0 - (T)];                                 \
                a1 += r[k][1] * F[4 + 1 - (T)];                                 \
                a2 += r[k][2] * F[4 + 2 - (T)];                                 \
                a3 += r[k][3] * F[4 + 3 - (T)];                                 \
            }                                                                   \
            float v0 = kh ? a0 : a2;                                            \
            float v1 = kh ? a1 : a3;                                            \
            float u0 = __shfl_xor_sync(0xffffffffu, v0, 1);                     \
            float u1 = __shfl_xor_sync(0xffffffffu, v1, 1);                     \
            if (active) {                                                       \
                float2 o;                                                       \
                if (kh == 0) { o.x = a0 + u0; o.y = a1 + u1; }                  \
                else         { o.x = a2 + u0; o.y = a3 + u1; }                  \
                stcs2(op, o);                                                   \
            }                                                                   \
            op += HH * WW;                                                      \
        }
        // group: preload PRE (no WAR hazard) then 4 sub-steps on (LO, HI)
#define GWC_GROUP(HI, LO, PRE, GIDX)                                            \
        {                                                                       \
            if ((GIDX) < DD / 4 - 1) {                                          \
                const int pp = P - 4 * ((GIDX) + 2);                            \
                _Pragma("unroll")                                               \
                for (int k = 0; k < 4; ++k)                                     \
                    PRE[k] = *(const float4*)(sbase + k * ROWA + pp);           \
            }                                                                   \
            GWC_STEP(LO, HI, 0) GWC_STEP(LO, HI, 1)                             \
            GWC_STEP(LO, HI, 2) GWC_STEP(LO, HI, 3)                             \
        }

#pragma unroll
        for (int gg = 0; gg < DD / 4; gg += 3) {
            GWC_GROUP(W0, W1, W2, gg)         // hi=W0 lo=W1, preload W2
            GWC_GROUP(W1, W2, W0, gg + 1)     // hi=W1 lo=W2, preload W0
            GWC_GROUP(W2, W0, W1, gg + 2)     // hi=W2 lo=W0, preload W1
        }
#undef GWC_GROUP
#undef GWC_STEP
    } else {
        // ======== concat block: one (c, d) plane, 120 threads ========
        const int d = wid_ % DD;
        const int c = wid_ / DD;
        if (tid >= 120) return;
        const int wq   = tid % 60;
        const int half = tid / 60;
        const int wb = wq * 4;
        const int h0 = half * 64;

        float* ob = out + ((((size_t)(NG + c) * DD + d) * HH) + h0) * WW + wb;

        if (c < 12) {
            const bool m0 = (wb + 0 >= d), m1 = (wb + 1 >= d),
                       m2 = (wb + 2 >= d), m3 = (wb + 3 >= d);
            const float* ib = refc + (((size_t)c * HH) + h0) * WW + wb;
#pragma unroll 4
            for (int h = 0; h < 64; ++h) {
                float4 x = *(const float4*)(ib + h * WW);
                float4 v;
                v.x = m0 ? x.x : 0.f;
                v.y = m1 ? x.y : 0.f;
                v.z = m2 ? x.z : 0.f;
                v.w = m3 ? x.w : 0.f;
                stcs4(ob + h * WW, v);
            }
        } else {
            // right-shifted tgt plane via aligned quad pair + uniform select
            const float* base = tgtc + (((size_t)(c - 12) * HH) + h0) * WW;
            const int sh = d & 3;
            if (sh == 0) {
                const int lo = wb - d;                 // quad aligned
                if (lo >= 0) {
                    const float* ib = base + lo;
#pragma unroll 4
                    for (int h = 0; h < 64; ++h)
                        stcs4(ob + h * WW, *(const float4*)(ib + h * WW));
                } else {
                    float4 z = make_float4(0.f, 0.f, 0.f, 0.f);
#pragma unroll 4
                    for (int h = 0; h < 64; ++h)
                        stcs4(ob + h * WW, z);
                }
            } else {
                const int off = 4 - sh;                // 1..3
                const int lo = wb - d - off;           // quad aligned
                const int hi4 = lo + 4;                // <= 236: in bounds when >=0
                const bool ldlo = (lo >= 0), ldhi = (hi4 >= 0);
                const float4 z = make_float4(0.f, 0.f, 0.f, 0.f);
#pragma unroll 4
                for (int h = 0; h < 64; ++h) {
                    float4 L = ldlo ? *(const float4*)(base + h * WW + lo)  : z;
                    float4 H = ldhi ? *(const float4*)(base + h * WW + hi4) : z;
                    float4 v;
                    if (off == 1)      { v.x = L.y; v.y = L.z; v.z = L.w; v.w = H.x; }
                    else if (off == 2) { v.x = L.z; v.y = L.w; v.z = H.x; v.w = H.y; }
                    else               { v.x = L.w; v.y = H.x; v.z = H.y; v.w = H.z; }
                    stcs4(ob + h * WW, v);
                }
            }
        }
    }
}

extern "C" void kernel_launch(void* const* d_in, const int* in_sizes, int n_in,
                              void* d_out, int out_size) {
    const float* ref_gwc    = (const float*)d_in[0];
    const float* tgt_gwc    = (const float*)d_in[1];
    const float* ref_concat = (const float*)d_in[2];
    const float* tgt_concat = (const float*)d_in[3];
    float* out = (float*)d_out;

    fused_kernel<<<TOTAL_BLOCKS, TPB>>>(ref_gwc, tgt_gwc, ref_concat, tgt_concat, out);
}